// round 5
// baseline (speedup 1.0000x reference)
#include <cuda_runtime.h>

// DenseGATConv collapses analytically:
//   out[b,i,c] = (1/H) * sum_h sum_f W_lin[f, h*C + c]
// B=8, N=1024, F=128, H=4, C=64. Output = one 64-float vector broadcast
// over 8192 rows.
//
// R5 structure: split the 64-float output vector into 4 column-groups of
// 16 floats (4 float4). Block = (row_chunk rc, col_group cg); it reads only
// the 32 KB of W_lin feeding its col-group (vs 128 KB for the full vector),
// reduces with warp butterflies, and stores its 4-float4 group for 256
// output rows. Grid 128 = 32 row-chunks x 4 col-groups.
// Inputs (metadata order): x[0], adj[1], diff[2], W_lin[3], w_diff[4],
//                          att_src[5], att_dst[6]

#define HC4 64   // W_lin row = 256 floats = 64 float4

__device__ __forceinline__ float4 f4add(float4 a, float4 b) {
    return make_float4(a.x + b.x, a.y + b.y, a.z + b.z, a.w + b.w);
}
__device__ __forceinline__ float4 f4shfl_xor(float4 v, int mask) {
    v.x = v.x + __shfl_xor_sync(0xffffffffu, v.x, mask);
    v.y = v.y + __shfl_xor_sync(0xffffffffu, v.y, mask);
    v.z = v.z + __shfl_xor_sync(0xffffffffu, v.z, mask);
    v.w = v.w + __shfl_xor_sync(0xffffffffu, v.w, mask);
    return v;
}

__global__ void __launch_bounds__(1024, 1)
gat_fused_kernel(const float4* __restrict__ W4, float4* __restrict__ out4) {
    __shared__ float4 part2[32][4];   // per-warp partials, by k
    __shared__ float4 g_s[4];         // this block's 4 output float4 (16 floats)

    const int t  = threadIdx.x;
    const int bx = blockIdx.x;
    const int cg = bx & 3;            // column group 0..3
    const int rc = bx >> 2;           // row chunk 0..31 (256 rows each)

    // ---- load: p = t encodes (f,h,k); each thread also takes f+64 ----
    const int k = t & 3;              // float4 within the group
    const int h = (t >> 2) & 3;       // head
    const int f = t >> 4;             // row 0..63
    const int base = f * HC4 + h * 16 + cg * 4 + k;
    float4 s = f4add(__ldg(&W4[base]), __ldg(&W4[base + 64 * HC4]));

    // ---- warp butterfly: fold f-pair (bit4) and h (bits 3,2) ----
    s = f4shfl_xor(s, 16);
    s = f4shfl_xor(s, 8);
    s = f4shfl_xor(s, 4);
    const int lane = t & 31;
    const int wid  = t >> 5;
    if (lane < 4) part2[wid][lane] = s;   // lane == k here
    __syncthreads();

    // ---- fold the 32 warp partials (one warp) ----
    if (t < 32) {
        const int k2 = t & 3;
        const int g  = t >> 2;            // 0..7
        float4 v = part2[g * 4 + 0][k2];
        v = f4add(v, part2[g * 4 + 1][k2]);
        v = f4add(v, part2[g * 4 + 2][k2]);
        v = f4add(v, part2[g * 4 + 3][k2]);
        v = f4shfl_xor(v, 4);             // fold g bits (lane bits 2..4)
        v = f4shfl_xor(v, 8);
        v = f4shfl_xor(v, 16);
        if (t < 4) {
            v.x *= 0.25f; v.y *= 0.25f; v.z *= 0.25f; v.w *= 0.25f;
            g_s[t] = v;
        }
    }
    __syncthreads();

    // ---- store: 256 rows x 4 float4 (this col-group), 1 STG.128/thread ----
    const int row = (rc << 8) + (t >> 2);
    out4[row * 16 + cg * 4 + (t & 3)] = g_s[t & 3];
}

extern "C" void kernel_launch(void* const* d_in, const int* in_sizes, int n_in,
                              void* d_out, int out_size) {
    const float4* W_lin4 = (const float4*)d_in[3];
    float4* out4 = (float4*)d_out;
    gat_fused_kernel<<<128, 1024>>>(W_lin4, out4);
}

// round 6
// speedup vs baseline: 1.0385x; 1.0385x over previous
#include <cuda_runtime.h>

// DenseGATConv collapses analytically:
//   out[b,i,c] = (1/H) * sum_h sum_f W_lin[f, h*C + c]
// B=8, N=1024, F=128, H=4, C=64. Output = one 64-float vector broadcast
// over 8192 rows.
//
// R6: latency-floor regime (interior work is hidden; only block width /
// barrier depth has ever moved the kernel time). 256-thread blocks (best
// measured config), col-group split (block reads 32 KB of W, not 128 KB),
// two warp-shuffle fold stages over just 8 warps, 4 STG.128 per thread.
// Grid 128 = 32 row-chunks x 4 col-groups.
// Inputs (metadata order): x[0], adj[1], diff[2], W_lin[3], w_diff[4],
//                          att_src[5], att_dst[6]

#define HC4 64   // W_lin row = 256 floats = 64 float4

__device__ __forceinline__ float4 f4shfl_xor(float4 v, int mask) {
    v.x += __shfl_xor_sync(0xffffffffu, v.x, mask);
    v.y += __shfl_xor_sync(0xffffffffu, v.y, mask);
    v.z += __shfl_xor_sync(0xffffffffu, v.z, mask);
    v.w += __shfl_xor_sync(0xffffffffu, v.w, mask);
    return v;
}

__global__ void __launch_bounds__(256, 1)
gat_fused_kernel(const float4* __restrict__ W4, float4* __restrict__ out4) {
    __shared__ float4 part[8][4];   // per-warp k-partials
    __shared__ float4 g_s[4];       // this block's 4 output float4

    const int t  = threadIdx.x;
    const int bx = blockIdx.x;
    const int cg = bx & 3;          // column group 0..3
    const int rc = bx >> 2;         // row chunk 0..31 (256 output rows each)

    // t encodes (f0, h, k): k = float4 within group, h = head, f0 = 0..15.
    const int k  = t & 3;
    const int h  = (t >> 2) & 3;
    const int f0 = t >> 4;
    const int col = h * 16 + cg * 4 + k;

    // Sum 8 rows (f = f0 + 16j): 8 LDG.128 in flight, one L2 round.
    float4 s = make_float4(0.f, 0.f, 0.f, 0.f);
#pragma unroll
    for (int j = 0; j < 8; ++j) {
        float4 v = __ldg(&W4[(f0 + 16 * j) * HC4 + col]);
        s.x += v.x; s.y += v.y; s.z += v.z; s.w += v.w;
    }

    // Fold f0-lsb (lane bit4) and h (lane bits 2-3) within the warp.
    s = f4shfl_xor(s, 16);
    s = f4shfl_xor(s, 8);
    s = f4shfl_xor(s, 4);
    const int lane = t & 31;
    const int wid  = t >> 5;
    if (lane < 4) part[wid][lane] = s;   // lane == k
    __syncthreads();

    // Warp 0 folds the 8 warp partials: lane = g*4 + k2, g = 0..7.
    if (t < 32) {
        float4 v = part[t >> 2][t & 3];
        v = f4shfl_xor(v, 4);
        v = f4shfl_xor(v, 8);
        v = f4shfl_xor(v, 16);
        if (t < 4) {
            v.x *= 0.25f; v.y *= 0.25f; v.z *= 0.25f; v.w *= 0.25f;
            g_s[t] = v;
        }
    }
    __syncthreads();

    // Store: block covers 256 rows x this col-group (4 float4/row).
    // Thread t: col k, rows r0 + 64*i.
    const float4 gv = g_s[k];
    const int r0 = t >> 2;
    float4* o = out4 + (size_t)(rc * 256 + r0) * 16 + cg * 4 + k;
#pragma unroll
    for (int i = 0; i < 4; ++i) o[i * 64 * 16] = gv;
}

extern "C" void kernel_launch(void* const* d_in, const int* in_sizes, int n_in,
                              void* d_out, int out_size) {
    const float4* W_lin4 = (const float4*)d_in[3];
    float4* out4 = (float4*)d_out;
    gat_fused_kernel<<<128, 256>>>(W_lin4, out4);
}

// round 7
// speedup vs baseline: 1.0485x; 1.0097x over previous
#include <cuda_runtime.h>

// DenseGATConv collapses analytically:
//   out[b,i,c] = (1/H) * sum_h sum_f W_lin[f, h*C + c]
// B=8, N=1024, F=128, H=4, C=64. Output = one 64-float vector broadcast
// over 8192 rows.
//
// R7: single-barrier critical path. 256-thread blocks, col-group split
// (block reads 32 KB of W), one in-warp 3-shuffle fold, ONE __syncthreads,
// then every thread folds the 8 warp partials itself via broadcast LDS
// (conflict-free) and stores. Grid 128 = 32 row-chunks x 4 col-groups.
// Inputs (metadata order): x[0], adj[1], diff[2], W_lin[3], w_diff[4],
//                          att_src[5], att_dst[6]

#define HC4 64   // W_lin row = 256 floats = 64 float4

__device__ __forceinline__ float4 f4shfl_xor(float4 v, int mask) {
    v.x += __shfl_xor_sync(0xffffffffu, v.x, mask);
    v.y += __shfl_xor_sync(0xffffffffu, v.y, mask);
    v.z += __shfl_xor_sync(0xffffffffu, v.z, mask);
    v.w += __shfl_xor_sync(0xffffffffu, v.w, mask);
    return v;
}

__global__ void __launch_bounds__(256, 1)
gat_fused_kernel(const float4* __restrict__ W4, float4* __restrict__ out4) {
    __shared__ float4 part[8][4];   // per-warp k-partials

    const int t  = threadIdx.x;
    const int bx = blockIdx.x;
    const int cg = bx & 3;          // column group 0..3
    const int rc = bx >> 2;         // row chunk 0..31 (256 output rows each)

    // t encodes (f0, h, k): k = float4 within group, h = head, f0 = 0..15.
    const int k  = t & 3;
    const int h  = (t >> 2) & 3;
    const int f0 = t >> 4;
    const int col = h * 16 + cg * 4 + k;

    // Sum 8 rows (f = f0 + 16j): 8 LDG.128 in flight, one L2 round.
    float4 s = make_float4(0.f, 0.f, 0.f, 0.f);
#pragma unroll
    for (int j = 0; j < 8; ++j) {
        float4 v = __ldg(&W4[(f0 + 16 * j) * HC4 + col]);
        s.x += v.x; s.y += v.y; s.z += v.z; s.w += v.w;
    }

    // In-warp fold of f0-lsb (bit4) and h (bits 3,2): partial lands at lane==k.
    s = f4shfl_xor(s, 16);
    s = f4shfl_xor(s, 8);
    s = f4shfl_xor(s, 4);
    const int lane = t & 31;
    const int wid  = t >> 5;
    if (lane < 4) part[wid][lane] = s;
    __syncthreads();

    // Every thread folds the 8 warp partials for its k (broadcast LDS, N=1).
    float4 g = part[0][k];
#pragma unroll
    for (int w = 1; w < 8; ++w) {
        float4 v = part[w][k];
        g.x += v.x; g.y += v.y; g.z += v.z; g.w += v.w;
    }
    g.x *= 0.25f; g.y *= 0.25f; g.z *= 0.25f; g.w *= 0.25f;

    // Store: block covers 256 rows x this col-group (4 float4/row).
    // Thread t: col k, rows r0 + 64*i.
    const int r0 = t >> 2;
    float4* o = out4 + (size_t)(rc * 256 + r0) * 16 + cg * 4 + k;
#pragma unroll
    for (int i = 0; i < 4; ++i) o[i * 64 * 16] = g;
}

extern "C" void kernel_launch(void* const* d_in, const int* in_sizes, int n_in,
                              void* d_out, int out_size) {
    const float4* W_lin4 = (const float4*)d_in[3];
    float4* out4 = (float4*)d_out;
    gat_fused_kernel<<<128, 256>>>(W_lin4, out4);
}